// round 1
// baseline (speedup 1.0000x reference)
#include <cuda_runtime.h>

static constexpr int N_OUT = 40962;
static constexpr int NIDX  = N_OUT * 7;          // 286734
static constexpr int OUTC  = 128;

// ---------------- device scratch (no allocations allowed) ----------------
__device__ int   g_neigh[NIDX];
__device__ int   g_pool[NIDX];
__device__ float g_pooled[(size_t)N_OUT * 64];
__device__ float g_t1[(size_t)N_OUT * OUTC];
__device__ float g_h [(size_t)N_OUT * OUTC];
__device__ float g_t2[(size_t)N_OUT * OUTC];
__device__ float g_part[256 * 256];              // per-block partial sums / sumsq
__device__ float g_bnp[256];                     // per-channel scale (0..127), shift (128..255)

// ---------------- index dtype detect + convert ----------------
// Reference does .astype(jnp.int64) but default JAX config keeps int32.
// If the buffer is int64 (little-endian, values < 2^31), every odd 32-bit word
// of the first 2048 words is zero; with real int32 index data that is
// (1/40962)^1024 improbable. Each block redundantly detects, then converts
// its stride of the array.
__global__ void convert_idx_kernel(const int* __restrict__ raw, int* __restrict__ out, int n) {
    __shared__ int s_is64;
    if (threadIdx.x == 0) s_is64 = 1;
    __syncthreads();
    for (int i = threadIdx.x; i < 1024; i += blockDim.x)
        if (raw[2 * i + 1] != 0) s_is64 = 0;
    __syncthreads();
    const int f = s_is64;
    for (int i = blockIdx.x * blockDim.x + threadIdx.x; i < n; i += gridDim.x * blockDim.x)
        out[i] = f ? raw[2 * i] : raw[i];
}

// ---------------- 1-ring mean pool with the reference's reshape scramble ----------------
// pooled[n,c] = (1/7) * sum_k flat[n*448 + c*7 + k], where flat[i*64+f] = x[pool[n*7+i]][f]
__global__ void __launch_bounds__(256) pool_kernel(const float* __restrict__ x) {
    __shared__ float sh[4][448];
    __shared__ int   srow[4][7];
    const int tid  = threadIdx.x;
    const int slot = tid >> 6;           // 0..3 (node within block)
    const int c    = tid & 63;           // channel
    const int node0 = blockIdx.x * 4;

    if (tid < 28) {
        int s = tid / 7, j = tid % 7;
        int node = node0 + s;
        srow[s][j] = (node < N_OUT) ? g_pool[node * 7 + j] : 0;
    }
    __syncthreads();
#pragma unroll
    for (int j = 0; j < 7; j++)
        sh[slot][j * 64 + c] = x[(size_t)srow[slot][j] * 64 + c];
    __syncthreads();

    const int node = node0 + slot;
    if (node < N_OUT) {
        float s = 0.f;
#pragma unroll
        for (int k = 0; k < 7; k++) s += sh[slot][c * 7 + k];
        g_pooled[(size_t)node * 64 + c] = s * (1.0f / 7.0f);
    }
}

// ---------------- gather-fused SGEMM: out[M,128] = gather(in)[M,7C] @ W[7C,128] + b ----------------
// BM=128, BN=128, BK=32, 256 threads, 8x8 microtile per thread.
template <int C>
__global__ void __launch_bounds__(256) gather_gemm(
    const float* __restrict__ in, const int* __restrict__ neigh,
    const float* __restrict__ W, const float* __restrict__ bias,
    float* __restrict__ out)
{
    constexpr int K  = 7 * C;
    constexpr int BM = 128, BN = 128, BK = 32;
    __shared__ float As[BK][BM + 4];     // [k][m], padded
    __shared__ float Bs[BK][BN];
    __shared__ int   rows[BM * 7];

    const int tid = threadIdx.x;
    const int m0  = blockIdx.x * BM;

    for (int i = tid; i < BM * 7; i += 256) {
        int node = m0 + (i / 7);
        rows[i] = (node < N_OUT) ? neigh[node * 7 + (i % 7)] : 0;
    }
    __syncthreads();

    float acc[8][8];
#pragma unroll
    for (int i = 0; i < 8; i++)
#pragma unroll
        for (int j = 0; j < 8; j++) acc[i][j] = 0.f;

    const int tm = (tid / 16) * 8;
    const int tn = (tid % 16) * 8;

    const int a_k = tid & 31;            // 0..31 (contiguous channel for coalescing)
    const int a_m = tid >> 5;            // 0..7
    const int b_n = tid & 127;
    const int b_k = tid >> 7;            // 0..1

    for (int k0 = 0; k0 < K; k0 += BK) {
        const int j  = k0 / C;           // neighbor slot (constant per tile: BK divides C)
        const int c0 = k0 % C;
#pragma unroll
        for (int p = 0; p < 16; p++) {
            int ml = a_m + p * 8;
            int src = rows[ml * 7 + j];
            As[a_k][ml] = in[(size_t)src * C + c0 + a_k];
        }
#pragma unroll
        for (int p = 0; p < 16; p++) {
            int kl = b_k + p * 2;
            Bs[kl][b_n] = W[(size_t)(k0 + kl) * BN + b_n];
        }
        __syncthreads();
#pragma unroll
        for (int kk = 0; kk < BK; kk++) {
            float4 a0 = *(const float4*)&As[kk][tm];
            float4 a1 = *(const float4*)&As[kk][tm + 4];
            float4 b0 = *(const float4*)&Bs[kk][tn];
            float4 b1 = *(const float4*)&Bs[kk][tn + 4];
            float a[8] = {a0.x, a0.y, a0.z, a0.w, a1.x, a1.y, a1.z, a1.w};
            float b[8] = {b0.x, b0.y, b0.z, b0.w, b1.x, b1.y, b1.z, b1.w};
#pragma unroll
            for (int i = 0; i < 8; i++)
#pragma unroll
                for (int jj = 0; jj < 8; jj++)
                    acc[i][jj] += a[i] * b[jj];
        }
        __syncthreads();
    }

    float4 bv0 = *(const float4*)&bias[tn];
    float4 bv1 = *(const float4*)&bias[tn + 4];
#pragma unroll
    for (int i = 0; i < 8; i++) {
        int m = m0 + tm + i;
        if (m < N_OUT) {
            float4 o0, o1;
            o0.x = acc[i][0] + bv0.x; o0.y = acc[i][1] + bv0.y;
            o0.z = acc[i][2] + bv0.z; o0.w = acc[i][3] + bv0.w;
            o1.x = acc[i][4] + bv1.x; o1.y = acc[i][5] + bv1.y;
            o1.z = acc[i][6] + bv1.z; o1.w = acc[i][7] + bv1.w;
            *(float4*)&out[(size_t)m * OUTC + tn]     = o0;
            *(float4*)&out[(size_t)m * OUTC + tn + 4] = o1;
        }
    }
}

// ---------------- deterministic batch-norm statistics ----------------
// Fixed grid of 256 blocks, 128 threads (thread = channel).
__global__ void stats_kernel(const float* __restrict__ t, int n_rows) {
    const int ch = threadIdx.x;
    float s = 0.f, ss = 0.f;
    for (int r = blockIdx.x; r < n_rows; r += gridDim.x) {
        float v = t[(size_t)r * OUTC + ch];
        s += v; ss += v * v;
    }
    g_part[blockIdx.x * 256 + ch]       = s;
    g_part[blockIdx.x * 256 + 128 + ch] = ss;
}

__global__ void finalize_kernel(const float* __restrict__ gamma,
                                const float* __restrict__ beta, int n_rows) {
    const int ch = threadIdx.x;  // 128 threads
    float s = 0.f, ss = 0.f;
    for (int b = 0; b < 256; b++) {
        s  += g_part[b * 256 + ch];
        ss += g_part[b * 256 + 128 + ch];
    }
    float m  = s / n_rows;
    float v  = ss / n_rows - m * m;          // biased variance
    float r  = rsqrtf(v + 1e-5f);
    float sc = r * gamma[ch];
    g_bnp[ch]       = sc;
    g_bnp[128 + ch] = beta[ch] - m * sc;
}

__global__ void bn_kernel(const float* __restrict__ t, float* __restrict__ out, int n_rows) {
    __shared__ float sc[128], sb[128];
    if (threadIdx.x < 128) {
        sc[threadIdx.x] = g_bnp[threadIdx.x];
        sb[threadIdx.x] = g_bnp[128 + threadIdx.x];
    }
    __syncthreads();
    const int total = n_rows * OUTC;
    for (int i = blockIdx.x * blockDim.x + threadIdx.x; i < total;
         i += gridDim.x * blockDim.x) {
        float y = t[i] * sc[i & 127] + sb[i & 127];
        out[i] = (y >= 0.f) ? y : 0.2f * y;
    }
}

// ---------------- launch ----------------
extern "C" void kernel_launch(void* const* d_in, const int* in_sizes, int n_in,
                              void* d_out, int out_size) {
    const float* x    = (const float*)d_in[0];
    const int*   nraw = (const int*)d_in[1];
    const int*   praw = (const int*)d_in[2];
    const float* W1   = (const float*)d_in[3];
    const float* b1   = (const float*)d_in[4];
    const float* g1   = (const float*)d_in[5];
    const float* be1  = (const float*)d_in[6];
    const float* W2   = (const float*)d_in[7];
    const float* b2   = (const float*)d_in[8];
    const float* g2   = (const float*)d_in[9];
    const float* be2  = (const float*)d_in[10];
    float* out = (float*)d_out;

    int *p_neigh, *p_pool;
    float *p_pooled, *p_t1, *p_h, *p_t2;
    cudaGetSymbolAddress((void**)&p_neigh,  g_neigh);
    cudaGetSymbolAddress((void**)&p_pool,   g_pool);
    cudaGetSymbolAddress((void**)&p_pooled, g_pooled);
    cudaGetSymbolAddress((void**)&p_t1,     g_t1);
    cudaGetSymbolAddress((void**)&p_h,      g_h);
    cudaGetSymbolAddress((void**)&p_t2,     g_t2);

    convert_idx_kernel<<<112, 256>>>(nraw, p_neigh, NIDX);
    convert_idx_kernel<<<112, 256>>>(praw, p_pool,  NIDX);

    pool_kernel<<<(N_OUT + 3) / 4, 256>>>(x);

    const int gemm_grid = (N_OUT + 127) / 128;   // 321
    gather_gemm<64><<<gemm_grid, 256>>>(p_pooled, p_neigh, W1, b1, p_t1);
    stats_kernel<<<256, 128>>>(p_t1, N_OUT);
    finalize_kernel<<<1, 128>>>(g1, be1, N_OUT);
    bn_kernel<<<512, 256>>>(p_t1, p_h, N_OUT);

    gather_gemm<128><<<gemm_grid, 256>>>(p_h, p_neigh, W2, b2, p_t2);
    stats_kernel<<<256, 128>>>(p_t2, N_OUT);
    finalize_kernel<<<1, 128>>>(g2, be2, N_OUT);
    bn_kernel<<<512, 256>>>(p_t2, out, N_OUT);
}

// round 2
// speedup vs baseline: 2.3169x; 2.3169x over previous
#include <cuda_runtime.h>
#include <cstdint>

static constexpr int N_OUT = 40962;
static constexpr int NIDX  = N_OUT * 7;          // 286734
static constexpr int OUTC  = 128;

// ---------------- device scratch (no allocations allowed) ----------------
__device__ int   g_neigh[NIDX];
__device__ int   g_pool[NIDX];
__device__ float g_pooled[(size_t)N_OUT * 64];
__device__ float g_t1[(size_t)N_OUT * OUTC];
__device__ float g_h [(size_t)N_OUT * OUTC];
__device__ float g_t2[(size_t)N_OUT * OUTC];
__device__ float g_part[256 * 256];              // per-block partial sums / sumsq
__device__ float g_bnp[256];                     // per-channel scale (0..127), shift (128..255)

// ---------------- index dtype detect + convert ----------------
__global__ void convert_idx_kernel(const int* __restrict__ raw, int* __restrict__ out, int n) {
    __shared__ int s_is64;
    if (threadIdx.x == 0) s_is64 = 1;
    __syncthreads();
    for (int i = threadIdx.x; i < 1024; i += blockDim.x)
        if (raw[2 * i + 1] != 0) s_is64 = 0;
    __syncthreads();
    const int f = s_is64;
    for (int i = blockIdx.x * blockDim.x + threadIdx.x; i < n; i += gridDim.x * blockDim.x)
        out[i] = f ? raw[2 * i] : raw[i];
}

// ---------------- 1-ring mean pool with the reference's reshape scramble ----------------
__global__ void __launch_bounds__(256) pool_kernel(const float* __restrict__ x) {
    __shared__ float sh[4][448];
    __shared__ int   srow[4][7];
    const int tid  = threadIdx.x;
    const int slot = tid >> 6;
    const int c    = tid & 63;
    const int node0 = blockIdx.x * 4;

    if (tid < 28) {
        int s = tid / 7, j = tid % 7;
        int node = node0 + s;
        srow[s][j] = (node < N_OUT) ? g_pool[node * 7 + j] : 0;
    }
    __syncthreads();
#pragma unroll
    for (int j = 0; j < 7; j++)
        sh[slot][j * 64 + c] = x[(size_t)srow[slot][j] * 64 + c];
    __syncthreads();

    const int node = node0 + slot;
    if (node < N_OUT) {
        float s = 0.f;
#pragma unroll
        for (int k = 0; k < 7; k++) s += sh[slot][c * 7 + k];
        g_pooled[(size_t)node * 64 + c] = s * (1.0f / 7.0f);
    }
}

// ---------------- tf32 helpers ----------------
__device__ __forceinline__ float f2tf32(float x) {
    uint32_t r;
    asm("cvt.rna.tf32.f32 %0, %1;" : "=r"(r) : "f"(x));
    return __uint_as_float(r);
}

__device__ __forceinline__ void mma_tf32(float* d, const uint32_t* a, const uint32_t* b) {
    asm volatile(
        "mma.sync.aligned.m16n8k8.row.col.f32.tf32.tf32.f32 "
        "{%0,%1,%2,%3}, {%4,%5,%6,%7}, {%8,%9}, {%0,%1,%2,%3};\n"
        : "+f"(d[0]), "+f"(d[1]), "+f"(d[2]), "+f"(d[3])
        : "r"(a[0]), "r"(a[1]), "r"(a[2]), "r"(a[3]), "r"(b[0]), "r"(b[1]));
}

// ---------------- gather-fused TF32 tensor GEMM ----------------
// out[M,128] = gather(in)[M,7C] @ W[7C,128] + bias.  BM=128, BN=128, BK=32.
// 8 warps in 4(M) x 2(N), warp tile 32x64, m16n8k8 fragments.
template <int C>
__global__ void __launch_bounds__(256, 2) gather_gemm_tf32(
    const float* __restrict__ in, const int* __restrict__ neigh,
    const float* __restrict__ W, const float* __restrict__ bias,
    float* __restrict__ out)
{
    constexpr int K = 7 * C;
    __shared__ __align__(16) float As[128][36];   // [m][k], stride 36 -> conflict-free frags
    __shared__ __align__(16) float Bs[32][136];   // [k][n], stride 136 -> conflict-free frags
    __shared__ int rows[128 * 7];

    const int tid  = threadIdx.x;
    const int m0   = blockIdx.x * 128;
    const int lane = tid & 31;
    const int wid  = tid >> 5;
    const int wm   = (wid & 3) * 32;   // warp m offset
    const int wn   = (wid >> 2) * 64;  // warp n offset
    const int g    = lane >> 2;
    const int tig  = lane & 3;

    for (int i = tid; i < 128 * 7; i += 256) {
        int node = m0 + (i / 7);
        rows[i] = (node < N_OUT) ? neigh[node * 7 + (i % 7)] : 0;
    }
    __syncthreads();

    float acc[2][8][4];
#pragma unroll
    for (int mt = 0; mt < 2; mt++)
#pragma unroll
        for (int nt = 0; nt < 8; nt++)
#pragma unroll
            for (int i = 0; i < 4; i++) acc[mt][nt][i] = 0.f;

    for (int k0 = 0; k0 < K; k0 += 32) {
        const int j  = k0 / C;           // neighbor slot (BK divides C -> constant per tile)
        const int c0 = k0 % C;

        // A: gather 128 rows x 32 ch.  1024 float4 / 256 threads = 4 each.
#pragma unroll
        for (int p = 0; p < 4; p++) {
            int q  = tid + p * 256;
            int m  = q >> 3;
            int kv = (q & 7) << 2;
            const float4 v = *(const float4*)&in[(size_t)rows[m * 7 + j] * C + c0 + kv];
            float4 t = {f2tf32(v.x), f2tf32(v.y), f2tf32(v.z), f2tf32(v.w)};
            *(float4*)&As[m][kv] = t;
        }
        // B: 32 rows x 128 cols of W.
#pragma unroll
        for (int p = 0; p < 4; p++) {
            int q   = tid + p * 256;
            int kl  = q >> 5;
            int col = (q & 31) << 2;
            const float4 v = *(const float4*)&W[(size_t)(k0 + kl) * 128 + col];
            float4 t = {f2tf32(v.x), f2tf32(v.y), f2tf32(v.z), f2tf32(v.w)};
            *(float4*)&Bs[kl][col] = t;
        }
        __syncthreads();

#pragma unroll
        for (int kk = 0; kk < 4; kk++) {
            const int kb = kk * 8;
            uint32_t a[2][4];
#pragma unroll
            for (int mt = 0; mt < 2; mt++) {
                int r = wm + mt * 16 + g;
                a[mt][0] = *(const uint32_t*)&As[r][kb + tig];
                a[mt][1] = *(const uint32_t*)&As[r + 8][kb + tig];
                a[mt][2] = *(const uint32_t*)&As[r][kb + tig + 4];
                a[mt][3] = *(const uint32_t*)&As[r + 8][kb + tig + 4];
            }
            uint32_t b[8][2];
#pragma unroll
            for (int nt = 0; nt < 8; nt++) {
                b[nt][0] = *(const uint32_t*)&Bs[kb + tig][wn + nt * 8 + g];
                b[nt][1] = *(const uint32_t*)&Bs[kb + tig + 4][wn + nt * 8 + g];
            }
#pragma unroll
            for (int mt = 0; mt < 2; mt++)
#pragma unroll
                for (int nt = 0; nt < 8; nt++)
                    mma_tf32(acc[mt][nt], a[mt], b[nt]);
        }
        __syncthreads();
    }

    // epilogue: + bias, store
#pragma unroll
    for (int mt = 0; mt < 2; mt++) {
        int r0 = m0 + wm + mt * 16 + g;
#pragma unroll
        for (int nt = 0; nt < 8; nt++) {
            int col = wn + nt * 8 + 2 * tig;
            float2 bv = *(const float2*)&bias[col];
            if (r0 < N_OUT) {
                float2 o = {acc[mt][nt][0] + bv.x, acc[mt][nt][1] + bv.y};
                *(float2*)&out[(size_t)r0 * OUTC + col] = o;
            }
            if (r0 + 8 < N_OUT) {
                float2 o = {acc[mt][nt][2] + bv.x, acc[mt][nt][3] + bv.y};
                *(float2*)&out[(size_t)(r0 + 8) * OUTC + col] = o;
            }
        }
    }
}

// ---------------- deterministic batch-norm statistics ----------------
__global__ void stats_kernel(const float* __restrict__ t, int n_rows) {
    const int ch = threadIdx.x;
    float s = 0.f, ss = 0.f;
    for (int r = blockIdx.x; r < n_rows; r += gridDim.x) {
        float v = t[(size_t)r * OUTC + ch];
        s += v; ss += v * v;
    }
    g_part[blockIdx.x * 256 + ch]       = s;
    g_part[blockIdx.x * 256 + 128 + ch] = ss;
}

__global__ void finalize_kernel(const float* __restrict__ gamma,
                                const float* __restrict__ beta, int n_rows) {
    const int ch = threadIdx.x;  // 128 threads
    float s = 0.f, ss = 0.f;
    for (int b = 0; b < 256; b++) {
        s  += g_part[b * 256 + ch];
        ss += g_part[b * 256 + 128 + ch];
    }
    float m  = s / n_rows;
    float v  = ss / n_rows - m * m;          // biased variance
    float r  = rsqrtf(v + 1e-5f);
    float sc = r * gamma[ch];
    g_bnp[ch]       = sc;
    g_bnp[128 + ch] = beta[ch] - m * sc;
}

__global__ void bn_kernel(const float* __restrict__ t, float* __restrict__ out, int n_rows) {
    __shared__ float sc[128], sb[128];
    if (threadIdx.x < 128) {
        sc[threadIdx.x] = g_bnp[threadIdx.x];
        sb[threadIdx.x] = g_bnp[128 + threadIdx.x];
    }
    __syncthreads();
    const int total = n_rows * OUTC;
    for (int i = blockIdx.x * blockDim.x + threadIdx.x; i < total;
         i += gridDim.x * blockDim.x) {
        float y = t[i] * sc[i & 127] + sb[i & 127];
        out[i] = (y >= 0.f) ? y : 0.2f * y;
    }
}

// ---------------- launch ----------------
extern "C" void kernel_launch(void* const* d_in, const int* in_sizes, int n_in,
                              void* d_out, int out_size) {
    const float* x    = (const float*)d_in[0];
    const int*   nraw = (const int*)d_in[1];
    const int*   praw = (const int*)d_in[2];
    const float* W1   = (const float*)d_in[3];
    const float* b1   = (const float*)d_in[4];
    const float* g1   = (const float*)d_in[5];
    const float* be1  = (const float*)d_in[6];
    const float* W2   = (const float*)d_in[7];
    const float* b2   = (const float*)d_in[8];
    const float* g2   = (const float*)d_in[9];
    const float* be2  = (const float*)d_in[10];
    float* out = (float*)d_out;

    int *p_neigh, *p_pool;
    float *p_pooled, *p_t1, *p_h, *p_t2;
    cudaGetSymbolAddress((void**)&p_neigh,  g_neigh);
    cudaGetSymbolAddress((void**)&p_pool,   g_pool);
    cudaGetSymbolAddress((void**)&p_pooled, g_pooled);
    cudaGetSymbolAddress((void**)&p_t1,     g_t1);
    cudaGetSymbolAddress((void**)&p_h,      g_h);
    cudaGetSymbolAddress((void**)&p_t2,     g_t2);

    convert_idx_kernel<<<112, 256>>>(nraw, p_neigh, NIDX);
    convert_idx_kernel<<<112, 256>>>(praw, p_pool,  NIDX);

    pool_kernel<<<(N_OUT + 3) / 4, 256>>>(x);

    const int gemm_grid = (N_OUT + 127) / 128;   // 321
    gather_gemm_tf32<64><<<gemm_grid, 256>>>(p_pooled, p_neigh, W1, b1, p_t1);
    stats_kernel<<<256, 128>>>(p_t1, N_OUT);
    finalize_kernel<<<1, 128>>>(g1, be1, N_OUT);
    bn_kernel<<<512, 256>>>(p_t1, p_h, N_OUT);

    gather_gemm_tf32<128><<<gemm_grid, 256>>>(p_h, p_neigh, W2, b2, p_t2);
    stats_kernel<<<256, 128>>>(p_t2, N_OUT);
    finalize_kernel<<<1, 128>>>(g2, be2, N_OUT);
    bn_kernel<<<512, 256>>>(p_t2, out, N_OUT);
}

// round 3
// speedup vs baseline: 3.6552x; 1.5776x over previous
#include <cuda_runtime.h>
#include <cstdint>

static constexpr int N_OUT = 40962;
static constexpr int NIDX  = N_OUT * 7;          // 286734
static constexpr int OUTC  = 128;
static constexpr int GEMM_GRID = (N_OUT + 127) / 128;   // 321

// ---------------- device scratch (no allocations allowed) ----------------
__device__ int   g_neigh[NIDX];
__device__ int   g_pool[NIDX];
__device__ float g_pooled[(size_t)N_OUT * 64];
__device__ float g_t1[(size_t)N_OUT * OUTC];
__device__ float g_h [(size_t)N_OUT * OUTC];
__device__ float g_t2[(size_t)N_OUT * OUTC];
__device__ float g_w1[448 * 128];
__device__ float g_w2[896 * 128];
__device__ float g_part[GEMM_GRID * 256];        // per-GEMM-block partial sum/sumsq
__device__ float g_bnp[256];                     // scale (0..127), shift (128..255)

// ---------------- helpers ----------------
__device__ __forceinline__ float f2tf32(float x) {
    uint32_t r;
    asm("cvt.rna.tf32.f32 %0, %1;" : "=r"(r) : "f"(x));
    return __uint_as_float(r);
}
__device__ __forceinline__ void mma_tf32(float* d, const uint32_t* a, const uint32_t* b) {
    asm volatile(
        "mma.sync.aligned.m16n8k8.row.col.f32.tf32.tf32.f32 "
        "{%0,%1,%2,%3}, {%4,%5,%6,%7}, {%8,%9}, {%0,%1,%2,%3};\n"
        : "+f"(d[0]), "+f"(d[1]), "+f"(d[2]), "+f"(d[3])
        : "r"(a[0]), "r"(a[1]), "r"(a[2]), "r"(a[3]), "r"(b[0]), "r"(b[1]));
}
__device__ __forceinline__ void cp16(float* smem_dst, const float* gsrc) {
    uint32_t s = (uint32_t)__cvta_generic_to_shared(smem_dst);
    asm volatile("cp.async.cg.shared.global [%0], [%1], 16;\n" :: "r"(s), "l"(gsrc));
}
__device__ __forceinline__ void cp_commit() { asm volatile("cp.async.commit_group;\n"); }
template <int N>
__device__ __forceinline__ void cp_wait() { asm volatile("cp.async.wait_group %0;\n" :: "n"(N)); }

// ---------------- index dtype detect + convert ----------------
__global__ void convert_idx_kernel(const int* __restrict__ raw, int* __restrict__ out, int n) {
    __shared__ int s_is64;
    if (threadIdx.x == 0) s_is64 = 1;
    __syncthreads();
    for (int i = threadIdx.x; i < 1024; i += blockDim.x)
        if (raw[2 * i + 1] != 0) s_is64 = 0;
    __syncthreads();
    const int f = s_is64;
    for (int i = blockIdx.x * blockDim.x + threadIdx.x; i < n; i += gridDim.x * blockDim.x)
        out[i] = f ? raw[2 * i] : raw[i];
}

// ---------------- weights -> tf32 ----------------
__global__ void wconv_kernel(const float* __restrict__ W1, const float* __restrict__ W2) {
    int i = blockIdx.x * blockDim.x + threadIdx.x;
    if (i < 448 * 128) g_w1[i] = f2tf32(W1[i]);
    else { int j = i - 448 * 128; if (j < 896 * 128) g_w2[j] = f2tf32(W2[j]); }
}

// ---------------- 1-ring mean pool (reference reshape scramble), tf32 output ----------------
__global__ void __launch_bounds__(256) pool_kernel(const float* __restrict__ x) {
    __shared__ float sh[4][448];
    __shared__ int   srow[4][7];
    const int tid  = threadIdx.x;
    const int slot = tid >> 6;
    const int c    = tid & 63;
    const int node0 = blockIdx.x * 4;

    if (tid < 28) {
        int s = tid / 7, j = tid % 7;
        int node = node0 + s;
        srow[s][j] = (node < N_OUT) ? g_pool[node * 7 + j] : 0;
    }
    __syncthreads();
#pragma unroll
    for (int j = 0; j < 7; j++)
        sh[slot][j * 64 + c] = x[(size_t)srow[slot][j] * 64 + c];
    __syncthreads();

    const int node = node0 + slot;
    if (node < N_OUT) {
        float s = 0.f;
#pragma unroll
        for (int k = 0; k < 7; k++) s += sh[slot][c * 7 + k];
        g_pooled[(size_t)node * 64 + c] = f2tf32(s * (1.0f / 7.0f));
    }
}

// ---------------- gather-fused TF32 GEMM, cp.async 2-stage, fused BN partials ----------------
// out[M,128] = gather(in)[M,7C] @ W[7C,128] + bias; per-block channel sum/sumsq -> g_part.
// in and W must be pre-rounded to tf32. BM=128, BN=128, BK=32; 8 warps 4(M)x2(N).
template <int C>
__global__ void __launch_bounds__(256, 2) gather_gemm_tf32(
    const float* __restrict__ in, const int* __restrict__ neigh,
    const float* __restrict__ W, const float* __restrict__ bias,
    float* __restrict__ out, float* __restrict__ part)
{
    constexpr int K   = 7 * C;
    constexpr int NT  = K / 32;
    constexpr int ASZ = 128 * 36;
    constexpr int BSZ = 32 * 136;
    constexpr int STG = ASZ + BSZ;

    extern __shared__ float smem[];          // 2 * STG floats
    __shared__ int   rows[128 * 7];
    __shared__ float red_s[4][128];
    __shared__ float red_q[4][128];

    const int tid  = threadIdx.x;
    const int m0   = blockIdx.x * 128;
    const int lane = tid & 31;
    const int wid  = tid >> 5;
    const int wm   = (wid & 3) * 32;
    const int wn   = (wid >> 2) * 64;
    const int g    = lane >> 2;
    const int tig  = lane & 3;

    for (int i = tid; i < 128 * 7; i += 256) {
        int node = m0 + (i / 7);
        rows[i] = (node < N_OUT) ? neigh[node * 7 + (i % 7)] : 0;
    }
    __syncthreads();

    auto issue = [&](int t) {
        const int k0 = t * 32;
        const int j  = k0 / C;
        const int c0 = k0 % C;
        float* dstA = smem + (t & 1) * STG;
        float* dstB = dstA + ASZ;
#pragma unroll
        for (int p = 0; p < 4; p++) {
            int q  = tid + p * 256;
            int m  = q >> 3;
            int kv = (q & 7) << 2;
            cp16(&dstA[m * 36 + kv], &in[(size_t)rows[m * 7 + j] * C + c0 + kv]);
        }
#pragma unroll
        for (int p = 0; p < 4; p++) {
            int q   = tid + p * 256;
            int kl  = q >> 5;
            int col = (q & 31) << 2;
            cp16(&dstB[kl * 136 + col], &W[(size_t)(k0 + kl) * 128 + col]);
        }
        cp_commit();
    };

    issue(0);
    issue(1);

    float acc[2][8][4];
#pragma unroll
    for (int mt = 0; mt < 2; mt++)
#pragma unroll
        for (int nt = 0; nt < 8; nt++)
#pragma unroll
            for (int i = 0; i < 4; i++) acc[mt][nt][i] = 0.f;

    for (int t = 0; t < NT; t++) {
        if (t < NT - 1) cp_wait<1>(); else cp_wait<0>();
        __syncthreads();

        const float* Ab = smem + (t & 1) * STG;
        const float* Bb = Ab + ASZ;
#pragma unroll
        for (int kk = 0; kk < 4; kk++) {
            const int kb = kk * 8;
            uint32_t a[2][4];
#pragma unroll
            for (int mt = 0; mt < 2; mt++) {
                int r = wm + mt * 16 + g;
                a[mt][0] = __float_as_uint(Ab[r * 36 + kb + tig]);
                a[mt][1] = __float_as_uint(Ab[(r + 8) * 36 + kb + tig]);
                a[mt][2] = __float_as_uint(Ab[r * 36 + kb + tig + 4]);
                a[mt][3] = __float_as_uint(Ab[(r + 8) * 36 + kb + tig + 4]);
            }
            uint32_t b[8][2];
#pragma unroll
            for (int nt = 0; nt < 8; nt++) {
                b[nt][0] = __float_as_uint(Bb[(kb + tig) * 136 + wn + nt * 8 + g]);
                b[nt][1] = __float_as_uint(Bb[(kb + tig + 4) * 136 + wn + nt * 8 + g]);
            }
#pragma unroll
            for (int mt = 0; mt < 2; mt++)
#pragma unroll
                for (int nt = 0; nt < 8; nt++)
                    mma_tf32(acc[mt][nt], a[mt], b[nt]);
        }
        __syncthreads();
        if (t + 2 < NT) issue(t + 2);
    }

    // ---- epilogue: bias, store, per-column sum/sumsq (valid rows only) ----
    float cs[16], cq[16];
#pragma unroll
    for (int i = 0; i < 16; i++) { cs[i] = 0.f; cq[i] = 0.f; }

#pragma unroll
    for (int mt = 0; mt < 2; mt++) {
        int r0 = m0 + wm + mt * 16 + g;
        bool v0 = r0 < N_OUT, v1 = (r0 + 8) < N_OUT;
#pragma unroll
        for (int nt = 0; nt < 8; nt++) {
            int col = wn + nt * 8 + 2 * tig;
            float2 bv = *(const float2*)&bias[col];
            float o00 = acc[mt][nt][0] + bv.x, o01 = acc[mt][nt][1] + bv.y;
            float o10 = acc[mt][nt][2] + bv.x, o11 = acc[mt][nt][3] + bv.y;
            if (v0) {
                *(float2*)&out[(size_t)r0 * OUTC + col] = make_float2(o00, o01);
                cs[nt*2]   += o00; cq[nt*2]   += o00 * o00;
                cs[nt*2+1] += o01; cq[nt*2+1] += o01 * o01;
            }
            if (v1) {
                *(float2*)&out[(size_t)(r0 + 8) * OUTC + col] = make_float2(o10, o11);
                cs[nt*2]   += o10; cq[nt*2]   += o10 * o10;
                cs[nt*2+1] += o11; cq[nt*2+1] += o11 * o11;
            }
        }
    }
    // reduce over g (lanes xor 4,8,16 keep tig fixed)
#pragma unroll
    for (int i = 0; i < 16; i++) {
#pragma unroll
        for (int d = 4; d < 32; d <<= 1) {
            cs[i] += __shfl_xor_sync(0xffffffffu, cs[i], d);
            cq[i] += __shfl_xor_sync(0xffffffffu, cq[i], d);
        }
    }
    if (lane < 4) {   // g == 0, tig = lane
#pragma unroll
        for (int nt = 0; nt < 8; nt++) {
            int col = wn + nt * 8 + 2 * lane;
            red_s[wid & 3][col]     = cs[nt*2];
            red_s[wid & 3][col + 1] = cs[nt*2+1];
            red_q[wid & 3][col]     = cq[nt*2];
            red_q[wid & 3][col + 1] = cq[nt*2+1];
        }
    }
    __syncthreads();
    if (tid < 128) {
        float s = red_s[0][tid] + red_s[1][tid] + red_s[2][tid] + red_s[3][tid];
        float q = red_q[0][tid] + red_q[1][tid] + red_q[2][tid] + red_q[3][tid];
        part[blockIdx.x * 256 + tid]       = s;
        part[blockIdx.x * 256 + 128 + tid] = q;
    }
}

// ---------------- BN finalize + apply ----------------
__global__ void finalize_kernel(const float* __restrict__ gamma,
                                const float* __restrict__ beta, int n_rows) {
    const int ch = threadIdx.x;  // 128 threads
    float s = 0.f, ss = 0.f;
    for (int b = 0; b < GEMM_GRID; b++) {
        s  += g_part[b * 256 + ch];
        ss += g_part[b * 256 + 128 + ch];
    }
    float m  = s / n_rows;
    float v  = ss / n_rows - m * m;          // biased variance
    float r  = rsqrtf(v + 1e-5f);
    float sc = r * gamma[ch];
    g_bnp[ch]       = sc;
    g_bnp[128 + ch] = beta[ch] - m * sc;
}

template <bool CVT>
__global__ void bn_kernel(const float* __restrict__ t, float* __restrict__ out, int n_rows) {
    __shared__ float sc[128], sb[128];
    if (threadIdx.x < 128) {
        sc[threadIdx.x] = g_bnp[threadIdx.x];
        sb[threadIdx.x] = g_bnp[128 + threadIdx.x];
    }
    __syncthreads();
    const int total = n_rows * OUTC;
    for (int i = blockIdx.x * blockDim.x + threadIdx.x; i < total;
         i += gridDim.x * blockDim.x) {
        float y = t[i] * sc[i & 127] + sb[i & 127];
        y = (y >= 0.f) ? y : 0.2f * y;
        out[i] = CVT ? f2tf32(y) : y;
    }
}

// ---------------- launch ----------------
extern "C" void kernel_launch(void* const* d_in, const int* in_sizes, int n_in,
                              void* d_out, int out_size) {
    const float* x    = (const float*)d_in[0];
    const int*   nraw = (const int*)d_in[1];
    const int*   praw = (const int*)d_in[2];
    const float* W1   = (const float*)d_in[3];
    const float* b1   = (const float*)d_in[4];
    const float* g1   = (const float*)d_in[5];
    const float* be1  = (const float*)d_in[6];
    const float* W2   = (const float*)d_in[7];
    const float* b2   = (const float*)d_in[8];
    const float* g2   = (const float*)d_in[9];
    const float* be2  = (const float*)d_in[10];
    float* out = (float*)d_out;

    int *p_neigh, *p_pool;
    float *p_pooled, *p_t1, *p_h, *p_t2, *p_w1, *p_w2, *p_part;
    cudaGetSymbolAddress((void**)&p_neigh,  g_neigh);
    cudaGetSymbolAddress((void**)&p_pool,   g_pool);
    cudaGetSymbolAddress((void**)&p_pooled, g_pooled);
    cudaGetSymbolAddress((void**)&p_t1,     g_t1);
    cudaGetSymbolAddress((void**)&p_h,      g_h);
    cudaGetSymbolAddress((void**)&p_t2,     g_t2);
    cudaGetSymbolAddress((void**)&p_w1,     g_w1);
    cudaGetSymbolAddress((void**)&p_w2,     g_w2);
    cudaGetSymbolAddress((void**)&p_part,   g_part);

    const int SMEM_DYN = 2 * (128 * 36 + 32 * 136) * (int)sizeof(float);  // 71680
    cudaFuncSetAttribute(gather_gemm_tf32<64>,
                         cudaFuncAttributeMaxDynamicSharedMemorySize, SMEM_DYN);
    cudaFuncSetAttribute(gather_gemm_tf32<128>,
                         cudaFuncAttributeMaxDynamicSharedMemorySize, SMEM_DYN);

    convert_idx_kernel<<<112, 256>>>(nraw, p_neigh, NIDX);
    convert_idx_kernel<<<112, 256>>>(praw, p_pool,  NIDX);
    wconv_kernel<<<(448 * 128 + 896 * 128 + 255) / 256, 256>>>(W1, W2);

    pool_kernel<<<(N_OUT + 3) / 4, 256>>>(x);

    gather_gemm_tf32<64><<<GEMM_GRID, 256, SMEM_DYN>>>(p_pooled, p_neigh, p_w1, b1, p_t1, p_part);
    finalize_kernel<<<1, 128>>>(g1, be1, N_OUT);
    bn_kernel<true><<<512, 256>>>(p_t1, p_h, N_OUT);

    gather_gemm_tf32<128><<<GEMM_GRID, 256, SMEM_DYN>>>(p_h, p_neigh, p_w2, b2, p_t2, p_part);
    finalize_kernel<<<1, 128>>>(g2, be2, N_OUT);
    bn_kernel<false><<<512, 256>>>(p_t2, out, N_OUT);
}